// round 15
// baseline (speedup 1.0000x reference)
#include <cuda_runtime.h>
#include <cuda_bf16.h>
#include <math.h>

// ---------------------------------------------------------------------------
// Static scratch (no allocation allowed).
// ---------------------------------------------------------------------------
__device__ __nv_bfloat16 g_Wc_hi[1024 * 1024];   // [D][U] bf16 hi
__device__ __nv_bfloat16 g_Wc_lo[1024 * 1024];
__device__ __nv_bfloat16 g_Wp_hi[1024 * 1024];   // [U][U]
__device__ __nv_bfloat16 g_Wp_lo[1024 * 1024];
// Double-buffered bf16 hi/lo copies of the recurrent state h [B=256][U=1024].
__device__ __nv_bfloat16 g_h_hi[2][256 * 1024];
__device__ __nv_bfloat16 g_h_lo[2][256 * 1024];

// ---------------------------------------------------------------------------
// Primitives.
// ---------------------------------------------------------------------------
__device__ __forceinline__ void ldsm4(unsigned r[4], unsigned addr) {
    asm volatile("ldmatrix.sync.aligned.m8n8.x4.shared.b16 {%0,%1,%2,%3}, [%4];"
                 : "=r"(r[0]), "=r"(r[1]), "=r"(r[2]), "=r"(r[3]) : "r"(addr));
}
__device__ __forceinline__ void ldsm4t(unsigned r[4], unsigned addr) {
    asm volatile("ldmatrix.sync.aligned.m8n8.x4.trans.shared.b16 {%0,%1,%2,%3}, [%4];"
                 : "=r"(r[0]), "=r"(r[1]), "=r"(r[2]), "=r"(r[3]) : "r"(addr));
}
__device__ __forceinline__ void mma16816(float d[4], const unsigned a[4],
                                         const unsigned b[2]) {
    asm volatile(
        "mma.sync.aligned.m16n8k16.row.col.f32.bf16.bf16.f32 "
        "{%0,%1,%2,%3}, {%4,%5,%6,%7}, {%8,%9}, {%0,%1,%2,%3};"
        : "+f"(d[0]), "+f"(d[1]), "+f"(d[2]), "+f"(d[3])
        : "r"(a[0]), "r"(a[1]), "r"(a[2]), "r"(a[3]), "r"(b[0]), "r"(b[1]));
}
__device__ __forceinline__ unsigned pack_bf(__nv_bfloat16 a, __nv_bfloat16 b) {
    unsigned short ua = *(unsigned short*)&a;
    unsigned short ub = *(unsigned short*)&b;
    return (unsigned)ua | ((unsigned)ub << 16);
}
__device__ __forceinline__ void split2(float v0, float v1,
                                       unsigned& hi, unsigned& lo) {
    __nv_bfloat16 h0 = __float2bfloat16_rn(v0);
    __nv_bfloat16 h1 = __float2bfloat16_rn(v1);
    __nv_bfloat16 l0 = __float2bfloat16_rn(v0 - __bfloat162float(h0));
    __nv_bfloat16 l1 = __float2bfloat16_rn(v1 - __bfloat162float(h1));
    hi = pack_bf(h0, h1);
    lo = pack_bf(l0, l1);
}
__device__ __forceinline__ void cpasync16(unsigned dst, const void* src) {
    asm volatile("cp.async.cg.shared.global [%0], [%1], 16;"
                 :: "r"(dst), "l"(src));
}
__device__ __forceinline__ void cp_commit() {
    asm volatile("cp.async.commit_group;");
}
__device__ __forceinline__ void cp_wait2() {
    asm volatile("cp.async.wait_group 2;");
}
__device__ __forceinline__ void cp_wait0() {
    asm volatile("cp.async.wait_group 0;");
}

// ---------------------------------------------------------------------------
// Build masked weights, split into bf16 hi/lo. One block per unit (column u).
// ---------------------------------------------------------------------------
__global__ void build_mask_kernel(const float* __restrict__ W,
                                  const float* __restrict__ mu,
                                  const float* __restrict__ sigma,
                                  __nv_bfloat16* __restrict__ Whi,
                                  __nv_bfloat16* __restrict__ Wlo,
                                  int n_in, int units, float scale) {
    int u = blockIdx.x;
    float m = mu[u];
    float s = sigma[u];
    s = fminf(fmaxf(s, 0.01f), 1.0f);
    float inv2s2 = 1.0f / (2.0f * s * s);
    float inv_nm1 = 1.0f / (float)(n_in - 1);

    float ss = 0.0f;
    for (int d = threadIdx.x; d < n_in; d += blockDim.x) {
        float diff = (float)d * inv_nm1 - m;
        float e = expf(-diff * diff * inv2s2);
        ss += e * e;
    }
    __shared__ float red[32];
    #pragma unroll
    for (int o = 16; o > 0; o >>= 1) ss += __shfl_down_sync(0xffffffffu, ss, o);
    if ((threadIdx.x & 31) == 0) red[threadIdx.x >> 5] = ss;
    __syncthreads();
    if (threadIdx.x < 32) {
        int nwarp = (blockDim.x + 31) >> 5;
        float v = (threadIdx.x < nwarp) ? red[threadIdx.x] : 0.0f;
        #pragma unroll
        for (int o = 16; o > 0; o >>= 1) v += __shfl_down_sync(0xffffffffu, v, o);
        if (threadIdx.x == 0) red[0] = v;
    }
    __syncthreads();
    float factor = scale * rsqrtf(red[0]);

    for (int d = threadIdx.x; d < n_in; d += blockDim.x) {
        float diff = (float)d * inv_nm1 - m;
        float e = expf(-diff * diff * inv2s2);
        float w = W[(size_t)d * units + u] * (e * factor);
        __nv_bfloat16 h = __float2bfloat16_rn(w);
        __nv_bfloat16 l = __float2bfloat16_rn(w - __bfloat162float(h));
        Whi[(size_t)d * units + u] = h;
        Wlo[(size_t)d * units + u] = l;
    }
}

// ---------------------------------------------------------------------------
// Convert h0 fp32 -> bf16 hi/lo planes.
// ---------------------------------------------------------------------------
__global__ void h0_split_kernel(const float* __restrict__ h0,
                                __nv_bfloat16* __restrict__ Hhi,
                                __nv_bfloat16* __restrict__ Hlo, int n) {
    int i = (blockIdx.x * blockDim.x + threadIdx.x) * 2;
    if (i < n) {
        unsigned hi, lo;
        split2(h0[i], h0[i + 1], hi, lo);
        *(unsigned*)((char*)Hhi + i * 2) = hi;
        *(unsigned*)((char*)Hlo + i * 2) = lo;
    }
}

// ---------------------------------------------------------------------------
// FUSED step kernel:
//   h_t = tanh( x_t @ Wc + bias + h_{t-1} @ Wp )   (3-term bf16 split each)
// BM=32, BN=64, 256 threads (8 warps: 2m x 4n), grid (U/64, B/32) = 128 CTAs.
//
// Phase H: K=1024 over Wp; A = h bf16 hi/lo planes; all via cp.async 4-stage,
//          one barrier per iter (R9-proven protocol).
// Phase X: K=1024 over Wc; B via cp.async 4-stage; A = x_t fp32 LDG -> split
//          -> STS into the A stage area, one iter lookahead. Stage s is
//          rewritten >=3 iters after its last reader crossed a barrier.
// Epilogue: +bias, tanh, store fp32 out + bf16 hi/lo h planes.
// SMEM: 4 stages x (2*32*144 + 2*64*144) = 110592 B.
// ---------------------------------------------------------------------------
__global__ void __launch_bounds__(256) fused_step(
    const float* __restrict__ Ax, size_t ldax,              // x_t, row stride T*D
    const __nv_bfloat16* __restrict__ Ahi_g,                // h_{t-1} planes
    const __nv_bfloat16* __restrict__ Alo_g,
    const __nv_bfloat16* __restrict__ Wch,
    const __nv_bfloat16* __restrict__ Wcl,
    const __nv_bfloat16* __restrict__ Wph,
    const __nv_bfloat16* __restrict__ Wpl,
    const float* __restrict__ bias,
    float* C, size_t ldc,                                   // out + t*U, stride T*U
    __nv_bfloat16* __restrict__ Hhi_o,
    __nv_bfloat16* __restrict__ Hlo_o,
    int N, int K)
{
    constexpr int PITCH = 144;
    constexpr int A_PL = 32 * PITCH;
    constexpr int B_PL = 64 * PITCH;
    constexpr int STAGE = 2 * A_PL + 2 * B_PL;   // 27648

    extern __shared__ char smem[];
    const unsigned sbase = (unsigned)__cvta_generic_to_shared(smem);

    const int tid  = threadIdx.x;
    const int lane = tid & 31;
    const int wid  = tid >> 5;
    const int wm   = wid & 1;
    const int wn   = wid >> 1;
    const int m0   = blockIdx.y * 32;
    const int n0   = blockIdx.x * 64;

    // ---- cp.async loaders ----
    auto issueB = [&](int st, int k0, const __nv_bfloat16* Bh,
                      const __nv_bfloat16* Bl) {
        const unsigned so = (unsigned)(st * STAGE);
        #pragma unroll
        for (int i = 0; i < 4; i++) {
            const int slot = tid + 256 * i;
            const int pl = slot >> 9;
            const int row = (slot & 511) >> 3, ch = slot & 7;
            const __nv_bfloat16* src = (pl ? Bl : Bh)
                + (size_t)(k0 + row) * N + n0 + ch * 8;
            cpasync16(sbase + so + (unsigned)(2 * A_PL + pl * B_PL + row * PITCH + ch * 16), src);
        }
    };
    auto issueAh = [&](int st, int k0) {
        const unsigned so = (unsigned)(st * STAGE);
        #pragma unroll
        for (int i = 0; i < 2; i++) {
            const int slot = (tid & 127) + 128 * i;
            const int row = slot >> 3, ch = slot & 7;
            const int pl = tid >> 7;
            const __nv_bfloat16* src = (pl ? Alo_g : Ahi_g)
                + (size_t)(m0 + row) * K + k0 + ch * 8;
            cpasync16(sbase + so + (unsigned)(pl * A_PL + row * PITCH + ch * 16), src);
        }
    };

    // ---- x_t fp32 loader: 32 rows x 64 k per stage; 8 floats per thread ----
    const int ax_row = tid >> 3;          // 0..31
    const int ax_kc  = (tid & 7) * 8;     // k offset (floats)
    float4 rx0, rx1;
    auto ldgAX = [&](int k0) {
        const float* p = Ax + (size_t)(m0 + ax_row) * ldax + k0 + ax_kc;
        rx0 = *(const float4*)p;
        rx1 = *(const float4*)(p + 4);
    };
    auto stsAX = [&](int st) {
        char* base = smem + st * STAGE + ax_row * PITCH + (tid & 7) * 16;
        unsigned h0, l0, h1, l1, h2, l2, h3, l3;
        split2(rx0.x, rx0.y, h0, l0);
        split2(rx0.z, rx0.w, h1, l1);
        split2(rx1.x, rx1.y, h2, l2);
        split2(rx1.z, rx1.w, h3, l3);
        *(uint4*)(base)        = make_uint4(h0, h1, h2, h3);
        *(uint4*)(base + A_PL) = make_uint4(l0, l1, l2, l3);
    };

    // ---- ldmatrix bases + compute ----
    const unsigned aBase = sbase + (unsigned)((wm * 16 + (lane & 15)) * PITCH
                                              + (lane >> 4) * 16);
    const unsigned bBase = sbase + (unsigned)(2 * A_PL + (lane & 15) * PITCH
                                              + (lane >> 4) * 16 + wn * 32);

    float accH[2][4], accX[2][4];
    #pragma unroll
    for (int j = 0; j < 2; j++)
        #pragma unroll
        for (int q = 0; q < 4; q++) { accH[j][q] = 0.f; accX[j][q] = 0.f; }

    auto compute = [&](int st) {
        const unsigned sOff = (unsigned)(st * STAGE);
        #pragma unroll
        for (int c = 0; c < 4; c++) {
            unsigned ah[4], al[4], bh[4], bl[4];
            ldsm4(ah, aBase + sOff + c * 32);
            ldsm4(al, aBase + sOff + A_PL + c * 32);
            ldsm4t(bh, bBase + sOff + c * (16 * PITCH));
            ldsm4t(bl, bBase + sOff + B_PL + c * (16 * PITCH));
            #pragma unroll
            for (int j = 0; j < 2; j++) {
                mma16816(accH[j], ah, bh + 2 * j);
                mma16816(accX[j], ah, bl + 2 * j);
                mma16816(accX[j], al, bh + 2 * j);
            }
        }
    };

    const int NIT = K / 64;   // 16 per phase

    // ================= Phase H: h_{t-1} @ Wp =================
    issueAh(0, 0);    issueB(0, 0, Wph, Wpl);    cp_commit();
    issueAh(1, 64);   issueB(1, 64, Wph, Wpl);   cp_commit();
    issueAh(2, 128);  issueB(2, 128, Wph, Wpl);  cp_commit();
    for (int it = 0; it < NIT; it++) {
        cp_wait2();
        __syncthreads();
        if (it + 3 < NIT) {
            issueAh((it + 3) & 3, (it + 3) * 64);
            issueB((it + 3) & 3, (it + 3) * 64, Wph, Wpl);
        }
        cp_commit();
        compute(it & 3);
    }

    // ---- transition: drain all cp groups, full barrier before reuse ----
    cp_wait0();
    __syncthreads();

    // ================= Phase X: x_t @ Wc =================
    ldgAX(0);
    stsAX(0);
    issueB(0, 0, Wch, Wcl);    cp_commit();
    issueB(1, 64, Wch, Wcl);   cp_commit();
    issueB(2, 128, Wch, Wcl);  cp_commit();
    for (int it = 0; it < NIT; it++) {
        cp_wait2();
        __syncthreads();
        if (it + 3 < NIT) issueB((it + 3) & 3, (it + 3) * 64, Wch, Wcl);
        cp_commit();
        if (it + 1 < NIT) ldgAX((it + 1) * 64);
        compute(it & 3);
        if (it + 1 < NIT) stsAX((it + 1) & 3);
        // stage (it+1)&3's previous readers (iter it-3) all crossed the
        // barrier at the top of iter it-2; STS here is safe. Visibility to
        // consumers is provided by the barrier at the top of iter it+1.
    }

    // ================= Epilogue =================
    const int mBase = m0 + wm * 16 + (lane >> 2);
    #pragma unroll
    for (int j = 0; j < 2; j++) {
        const int nBase = n0 + wn * 16 + j * 8 + 2 * (lane & 3);
        const float b0 = bias[nBase];
        const float b1 = bias[nBase + 1];
        #pragma unroll
        for (int h = 0; h < 2; h++) {
            const int m = mBase + h * 8;
            float d0 = accH[j][2 * h + 0] + accX[j][2 * h + 0] + b0;
            float d1 = accH[j][2 * h + 1] + accX[j][2 * h + 1] + b1;
            float o0 = tanhf(d0);
            float o1 = tanhf(d1);
            *(float2*)(C + (size_t)m * ldc + nBase) = make_float2(o0, o1);
            unsigned hi, lo;
            split2(o0, o1, hi, lo);
            *(unsigned*)((char*)Hhi_o + ((size_t)m * N + nBase) * 2) = hi;
            *(unsigned*)((char*)Hlo_o + ((size_t)m * N + nBase) * 2) = lo;
        }
    }
}

// ---------------------------------------------------------------------------
// Launch.
// Inputs: 0 inputs [B,T,D]  1 h0 [B,U]  2 kernel [D,U]  3 rec_kernel [U,U]
//         4 bias [U]  5 mu_c [U]  6 sigma_c [U]  7 mu_p [U]  8 sigma_p [U]
// Output: [B,T,U] float32.
// ---------------------------------------------------------------------------
extern "C" void kernel_launch(void* const* d_in, const int* in_sizes, int n_in,
                              void* d_out, int out_size) {
    const float* X    = (const float*)d_in[0];
    const float* h0   = (const float*)d_in[1];
    const float* Wk   = (const float*)d_in[2];
    const float* Wr   = (const float*)d_in[3];
    const float* bias = (const float*)d_in[4];
    const float* muc  = (const float*)d_in[5];
    const float* sic  = (const float*)d_in[6];
    const float* mup  = (const float*)d_in[7];
    const float* sip  = (const float*)d_in[8];
    float* out = (float*)d_out;

    const int U = in_sizes[4];
    const int D = in_sizes[2] / U;
    const int B = in_sizes[1] / U;
    const int T = in_sizes[0] / (B * D);

    __nv_bfloat16 *Wc_hi, *Wc_lo, *Wp_hi, *Wp_lo, *Hhi, *Hlo;
    cudaGetSymbolAddress((void**)&Wc_hi, g_Wc_hi);
    cudaGetSymbolAddress((void**)&Wc_lo, g_Wc_lo);
    cudaGetSymbolAddress((void**)&Wp_hi, g_Wp_hi);
    cudaGetSymbolAddress((void**)&Wp_lo, g_Wp_lo);
    cudaGetSymbolAddress((void**)&Hhi, g_h_hi);
    cudaGetSymbolAddress((void**)&Hlo, g_h_lo);
    const size_t HPLANE = (size_t)256 * 1024;

    const int SMEM_STEP = 4 * (2 * 32 * 144 + 2 * 64 * 144);   // 110592
    static int s_init_done = 0;
    if (!s_init_done) {
        cudaFuncSetAttribute(fused_step,
                             cudaFuncAttributeMaxDynamicSharedMemorySize, SMEM_STEP);
        s_init_done = 1;
    }

    const float scale = sqrtf((float)D);  // reference uses sqrt(D) for BOTH masks

    // 1) Masked weights, split to bf16 hi/lo; h0 split into buffer 1.
    build_mask_kernel<<<U, 256>>>(Wk, muc, sic, Wc_hi, Wc_lo, D, U, scale);
    build_mask_kernel<<<U, 256>>>(Wr, mup, sip, Wp_hi, Wp_lo, U, U, scale);
    {
        int n = B * U;
        h0_split_kernel<<<(n / 2 + 255) / 256, 256>>>(
            h0, Hhi + HPLANE, Hlo + HPLANE, n);
    }

    // 2) Fused scan: one kernel per timestep does x_t@Wc + h@Wp + tanh.
    {
        dim3 grid(U / 64, B / 32);           // 16 x 8 = 128 CTAs (one wave)
        const size_t ldo = (size_t)T * U;
        const size_t ldx = (size_t)T * D;
        for (int t = 0; t < T; t++) {
            const int rb = (t + 1) & 1;
            const int wb = t & 1;
            fused_step<<<grid, 256, SMEM_STEP>>>(
                X + (size_t)t * D, ldx,
                Hhi + rb * HPLANE, Hlo + rb * HPLANE,
                Wc_hi, Wc_lo, Wp_hi, Wp_lo,
                bias,
                out + (size_t)t * U, ldo,
                Hhi + wb * HPLANE, Hlo + wb * HPLANE,
                U, U);
        }
    }
}

// round 17
// speedup vs baseline: 1.5010x; 1.5010x over previous
#include <cuda_runtime.h>
#include <cuda_bf16.h>
#include <math.h>

// ---------------------------------------------------------------------------
// Static scratch (no allocation allowed).
// ---------------------------------------------------------------------------
__device__ __nv_bfloat16 g_Wc_hi[1024 * 1024];
__device__ __nv_bfloat16 g_Wc_lo[1024 * 1024];
__device__ __nv_bfloat16 g_Wp_hi[1024 * 1024];
__device__ __nv_bfloat16 g_Wp_lo[1024 * 1024];
// Double-buffered bf16 hi/lo copies of the recurrent state h [B=256][U=1024].
__device__ __nv_bfloat16 g_h_hi[2][256 * 1024];
__device__ __nv_bfloat16 g_h_lo[2][256 * 1024];

// ---------------------------------------------------------------------------
// Primitives.
// ---------------------------------------------------------------------------
__device__ __forceinline__ void ldsm4(unsigned r[4], unsigned addr) {
    asm volatile("ldmatrix.sync.aligned.m8n8.x4.shared.b16 {%0,%1,%2,%3}, [%4];"
                 : "=r"(r[0]), "=r"(r[1]), "=r"(r[2]), "=r"(r[3]) : "r"(addr));
}
__device__ __forceinline__ void ldsm4t(unsigned r[4], unsigned addr) {
    asm volatile("ldmatrix.sync.aligned.m8n8.x4.trans.shared.b16 {%0,%1,%2,%3}, [%4];"
                 : "=r"(r[0]), "=r"(r[1]), "=r"(r[2]), "=r"(r[3]) : "r"(addr));
}
__device__ __forceinline__ void mma16816(float d[4], const unsigned a[4],
                                         const unsigned b[2]) {
    asm volatile(
        "mma.sync.aligned.m16n8k16.row.col.f32.bf16.bf16.f32 "
        "{%0,%1,%2,%3}, {%4,%5,%6,%7}, {%8,%9}, {%0,%1,%2,%3};"
        : "+f"(d[0]), "+f"(d[1]), "+f"(d[2]), "+f"(d[3])
        : "r"(a[0]), "r"(a[1]), "r"(a[2]), "r"(a[3]), "r"(b[0]), "r"(b[1]));
}
__device__ __forceinline__ unsigned pack_bf(__nv_bfloat16 a, __nv_bfloat16 b) {
    unsigned short ua = *(unsigned short*)&a;
    unsigned short ub = *(unsigned short*)&b;
    return (unsigned)ua | ((unsigned)ub << 16);
}
__device__ __forceinline__ void split2(float v0, float v1,
                                       unsigned& hi, unsigned& lo) {
    __nv_bfloat16 h0 = __float2bfloat16_rn(v0);
    __nv_bfloat16 h1 = __float2bfloat16_rn(v1);
    __nv_bfloat16 l0 = __float2bfloat16_rn(v0 - __bfloat162float(h0));
    __nv_bfloat16 l1 = __float2bfloat16_rn(v1 - __bfloat162float(h1));
    hi = pack_bf(h0, h1);
    lo = pack_bf(l0, l1);
}
__device__ __forceinline__ void cpasync16(unsigned dst, const void* src) {
    asm volatile("cp.async.cg.shared.global [%0], [%1], 16;"
                 :: "r"(dst), "l"(src));
}
__device__ __forceinline__ void cp_commit() {
    asm volatile("cp.async.commit_group;");
}
__device__ __forceinline__ void cp_wait1() {
    asm volatile("cp.async.wait_group 1;");
}

// ---------------------------------------------------------------------------
// Build masked weights, split into bf16 hi/lo. One block per unit (column u).
// ---------------------------------------------------------------------------
__global__ void build_mask_kernel(const float* __restrict__ W,
                                  const float* __restrict__ mu,
                                  const float* __restrict__ sigma,
                                  __nv_bfloat16* __restrict__ Whi,
                                  __nv_bfloat16* __restrict__ Wlo,
                                  int n_in, int units, float scale) {
    int u = blockIdx.x;
    float m = mu[u];
    float s = sigma[u];
    s = fminf(fmaxf(s, 0.01f), 1.0f);
    float inv2s2 = 1.0f / (2.0f * s * s);
    float inv_nm1 = 1.0f / (float)(n_in - 1);

    float ss = 0.0f;
    for (int d = threadIdx.x; d < n_in; d += blockDim.x) {
        float diff = (float)d * inv_nm1 - m;
        float e = expf(-diff * diff * inv2s2);
        ss += e * e;
    }
    __shared__ float red[32];
    #pragma unroll
    for (int o = 16; o > 0; o >>= 1) ss += __shfl_down_sync(0xffffffffu, ss, o);
    if ((threadIdx.x & 31) == 0) red[threadIdx.x >> 5] = ss;
    __syncthreads();
    if (threadIdx.x < 32) {
        int nwarp = (blockDim.x + 31) >> 5;
        float v = (threadIdx.x < nwarp) ? red[threadIdx.x] : 0.0f;
        #pragma unroll
        for (int o = 16; o > 0; o >>= 1) v += __shfl_down_sync(0xffffffffu, v, o);
        if (threadIdx.x == 0) red[0] = v;
    }
    __syncthreads();
    float factor = scale * rsqrtf(red[0]);

    for (int d = threadIdx.x; d < n_in; d += blockDim.x) {
        float diff = (float)d * inv_nm1 - m;
        float e = expf(-diff * diff * inv2s2);
        float w = W[(size_t)d * units + u] * (e * factor);
        __nv_bfloat16 h = __float2bfloat16_rn(w);
        __nv_bfloat16 l = __float2bfloat16_rn(w - __bfloat162float(h));
        Whi[(size_t)d * units + u] = h;
        Wlo[(size_t)d * units + u] = l;
    }
}

// ---------------------------------------------------------------------------
// Convert h0 fp32 -> bf16 hi/lo planes.
// ---------------------------------------------------------------------------
__global__ void h0_split_kernel(const float* __restrict__ h0,
                                __nv_bfloat16* __restrict__ Hhi,
                                __nv_bfloat16* __restrict__ Hlo, int n) {
    int i = (blockIdx.x * blockDim.x + threadIdx.x) * 2;
    if (i < n) {
        unsigned hi, lo;
        split2(h0[i], h0[i + 1], hi, lo);
        *(unsigned*)((char*)Hhi + i * 2) = hi;
        *(unsigned*)((char*)Hlo + i * 2) = lo;
    }
}

// ---------------------------------------------------------------------------
// Big GEMM v2: BM=64, BN=64, BK=32, 128 threads, 4 warps (2m x 2n),
// warp tile 32x32 -> 8 LDSM per 24 MMAs (halved L1 ldmatrix traffic).
// SMEM 47104 B -> up to 4 CTAs/SM.
// ---------------------------------------------------------------------------
__global__ void __launch_bounds__(128) mma_gemm_big(
    const float* A, size_t lda,
    const __nv_bfloat16* __restrict__ Bhi_g,
    const __nv_bfloat16* __restrict__ Blo_g,
    const float* __restrict__ bias,
    float* C, size_t ldc, int N, int K)
{
    constexpr int APITCH = 112;
    constexpr int BPITCH = 144;
    constexpr int A_PL = 64 * APITCH;
    constexpr int B_PL = 32 * BPITCH;
    constexpr int STAGE = 2 * A_PL + 2 * B_PL;

    extern __shared__ char smem[];
    const unsigned sbase = (unsigned)__cvta_generic_to_shared(smem);

    const int tid  = threadIdx.x;
    const int lane = tid & 31;
    const int wid  = tid >> 5;
    const int wm   = wid & 1;                  // 0..1 -> m32
    const int wn   = wid >> 1;                 // 0..1 -> n32
    const int m0   = blockIdx.y * 64;
    const int n0   = blockIdx.x * 64;

    float4 ra[4];
    uint4  rbh[2], rbl[2];

    const unsigned aBase = sbase + (unsigned)((wm * 32 + (lane & 15)) * APITCH
                                              + (lane >> 4) * 16);
    const unsigned bBase = sbase + (unsigned)(2 * A_PL + (lane & 15) * BPITCH
                                              + (lane >> 4) * 16 + wn * 64);

    float accH[2][4][4], accX[2][4][4];
    #pragma unroll
    for (int i = 0; i < 2; i++)
        #pragma unroll
        for (int j = 0; j < 4; j++)
            #pragma unroll
            for (int q = 0; q < 4; q++) { accH[i][j][q] = 0.f; accX[i][j][q] = 0.f; }

    // Loaders (128 threads): A 64x32 fp32 -> 16 floats/thread.
    const int aRow = tid >> 1;            // 0..63
    const int aKc  = (tid & 1) * 16;      // k offset (floats)
    auto ldgA = [&](int k0) {
        const float* p = A + (size_t)(m0 + aRow) * lda + k0 + aKc;
        ra[0] = *(const float4*)p;
        ra[1] = *(const float4*)(p + 4);
        ra[2] = *(const float4*)(p + 8);
        ra[3] = *(const float4*)(p + 12);
    };
    const int bRow = tid >> 2;            // 0..31
    const int bNc  = (tid & 3) * 16;      // n offset (elems)
    auto ldgB = [&](int k0) {
        size_t off = (size_t)(k0 + bRow) * N + n0 + bNc;
        rbh[0] = *(const uint4*)(Bhi_g + off);
        rbh[1] = *(const uint4*)(Bhi_g + off + 8);
        rbl[0] = *(const uint4*)(Blo_g + off);
        rbl[1] = *(const uint4*)(Blo_g + off + 8);
    };
    auto stsAB = [&](int st) {
        char* base = smem + st * STAGE;
        #pragma unroll
        for (int g = 0; g < 2; g++) {     // two 8-float groups
            const int kc = aKc + 8 * g;
            unsigned h0, l0, h1, l1, h2, l2, h3, l3;
            split2(ra[2*g].x, ra[2*g].y, h0, l0);
            split2(ra[2*g].z, ra[2*g].w, h1, l1);
            split2(ra[2*g+1].x, ra[2*g+1].y, h2, l2);
            split2(ra[2*g+1].z, ra[2*g+1].w, h3, l3);
            *(uint4*)(base + aRow * APITCH + kc * 2)        = make_uint4(h0, h1, h2, h3);
            *(uint4*)(base + A_PL + aRow * APITCH + kc * 2) = make_uint4(l0, l1, l2, l3);
        }
        *(uint4*)(base + 2 * A_PL + bRow * BPITCH + bNc * 2)               = rbh[0];
        *(uint4*)(base + 2 * A_PL + bRow * BPITCH + bNc * 2 + 16)          = rbh[1];
        *(uint4*)(base + 2 * A_PL + B_PL + bRow * BPITCH + bNc * 2)        = rbl[0];
        *(uint4*)(base + 2 * A_PL + B_PL + bRow * BPITCH + bNc * 2 + 16)   = rbl[1];
    };
    auto compute = [&](int st) {
        const unsigned sOff = (unsigned)(st * STAGE);
        #pragma unroll
        for (int c = 0; c < 2; c++) {
            unsigned ah[2][4], al[2][4], bh[2][4], bl[2][4];
            #pragma unroll
            for (int i = 0; i < 2; i++) {
                ldsm4(ah[i], aBase + sOff + i * (16 * APITCH) + c * 32);
                ldsm4(al[i], aBase + sOff + A_PL + i * (16 * APITCH) + c * 32);
            }
            #pragma unroll
            for (int jj = 0; jj < 2; jj++) {
                ldsm4t(bh[jj], bBase + sOff + c * (16 * BPITCH) + jj * 32);
                ldsm4t(bl[jj], bBase + sOff + B_PL + c * (16 * BPITCH) + jj * 32);
            }
            #pragma unroll
            for (int i = 0; i < 2; i++)
                #pragma unroll
                for (int jj = 0; jj < 2; jj++)
                    #pragma unroll
                    for (int j = 0; j < 2; j++) {
                        mma16816(accH[i][jj * 2 + j], ah[i], bh[jj] + 2 * j);
                        mma16816(accX[i][jj * 2 + j], ah[i], bl[jj] + 2 * j);
                        mma16816(accX[i][jj * 2 + j], al[i], bh[jj] + 2 * j);
                    }
        }
    };

    const int NIT = K / 32;
    ldgA(0); ldgB(0);
    stsAB(0);
    __syncthreads();
    int s = 0;
    for (int it = 0; it < NIT; it++) {
        if (it + 1 < NIT) { ldgA((it + 1) * 32); ldgB((it + 1) * 32); }
        compute(s);
        if (it + 1 < NIT) {
            stsAB(s ^ 1);
            __syncthreads();
            s ^= 1;
        }
    }

    #pragma unroll
    for (int i = 0; i < 2; i++) {
        const int mBase = m0 + wm * 32 + i * 16 + (lane >> 2);
        #pragma unroll
        for (int jj = 0; jj < 2; jj++)
            #pragma unroll
            for (int j = 0; j < 2; j++) {
                const int nBase = n0 + wn * 32 + jj * 16 + j * 8 + 2 * (lane & 3);
                const int aj = jj * 2 + j;
                #pragma unroll
                for (int h = 0; h < 2; h++) {
                    const int m = mBase + h * 8;
                    float d0 = accH[i][aj][2 * h + 0] + accX[i][aj][2 * h + 0];
                    float d1 = accH[i][aj][2 * h + 1] + accX[i][aj][2 * h + 1];
                    float2 o;
                    o.x = d0 + bias[nBase];
                    o.y = d1 + bias[nBase + 1];
                    *(float2*)(C + (size_t)m * ldc + nBase) = o;
                }
            }
    }
}

// ---------------------------------------------------------------------------
// Step GEMM v5: bf16 operands, cp.async 3-stage ring, BK=128 -> 8 iterations,
// 8 barriers per step.  C = tanh(C + Ah@Bh + Ah@Bl + Al@Bh) in place,
// also writes bf16 hi/lo h for the next step.
// BM=32, BN=64, 256 threads (8 warps: 2m x 4n), grid 128 CTAs.
// SMEM/stage: A 2*32*272 + B 2*128*144 = 54272 B; 3 stages = 162816 B.
// ---------------------------------------------------------------------------
__global__ void __launch_bounds__(256) mma_gemm_step(
    const __nv_bfloat16* __restrict__ Ahi_g,
    const __nv_bfloat16* __restrict__ Alo_g,
    const __nv_bfloat16* __restrict__ Bhi_g,
    const __nv_bfloat16* __restrict__ Blo_g,
    float* C, size_t ldc,
    __nv_bfloat16* __restrict__ Hhi_o,
    __nv_bfloat16* __restrict__ Hlo_o,
    int N, int K)
{
    constexpr int APITCH = 272;                // 128 bf16 = 256B + 16 pad
    constexpr int BPITCH = 144;                // 64 bf16 = 128B + 16 pad
    constexpr int A_PL = 32 * APITCH;          // 8704
    constexpr int B_PL = 128 * BPITCH;         // 18432
    constexpr int STAGE = 2 * A_PL + 2 * B_PL; // 54272

    extern __shared__ char smem[];
    const unsigned sbase = (unsigned)__cvta_generic_to_shared(smem);

    const int tid  = threadIdx.x;
    const int lane = tid & 31;
    const int wid  = tid >> 5;
    const int wm   = wid & 1;
    const int wn   = wid >> 1;
    const int m0   = blockIdx.y * 32;
    const int n0   = blockIdx.x * 64;

    auto issue_stage = [&](int st, int k0) {
        const unsigned so = (unsigned)(st * STAGE);
        // A: 2 planes x 32 rows x 16 chunks = 1024 slots -> 4/thread.
        #pragma unroll
        for (int i = 0; i < 4; i++) {
            const int slot = tid + 256 * i;
            const int pl = slot >> 9;
            const int row = (slot & 511) >> 4, ch = slot & 15;
            const __nv_bfloat16* src = (pl ? Alo_g : Ahi_g)
                + (size_t)(m0 + row) * K + k0 + ch * 8;
            cpasync16(sbase + so + (unsigned)(pl * A_PL + row * APITCH + ch * 16), src);
        }
        // B: 2 planes x 128 rows x 8 chunks = 2048 slots -> 8/thread.
        #pragma unroll
        for (int i = 0; i < 8; i++) {
            const int slot = tid + 256 * i;
            const int pl = slot >> 10;
            const int row = (slot & 1023) >> 3, ch = slot & 7;
            const __nv_bfloat16* src = (pl ? Blo_g : Bhi_g)
                + (size_t)(k0 + row) * N + n0 + ch * 8;
            cpasync16(sbase + so + (unsigned)(2 * A_PL + pl * B_PL + row * BPITCH + ch * 16), src);
        }
    };

    const unsigned aBase = sbase + (unsigned)((wm * 16 + (lane & 15)) * APITCH
                                              + (lane >> 4) * 16);
    const unsigned bBase = sbase + (unsigned)(2 * A_PL + (lane & 15) * BPITCH
                                              + (lane >> 4) * 16 + wn * 32);

    float accH[2][4], accX[2][4];
    #pragma unroll
    for (int j = 0; j < 2; j++)
        #pragma unroll
        for (int q = 0; q < 4; q++) { accH[j][q] = 0.f; accX[j][q] = 0.f; }

    const int NIT = K / 128;                   // 8
    issue_stage(0, 0);    cp_commit();
    issue_stage(1, 128);  cp_commit();

    for (int it = 0; it < NIT; it++) {
        cp_wait1();
        __syncthreads();       // stage it%3 visible; all warps past iter it-1
        if (it + 2 < NIT) issue_stage((it + 2) % 3, (it + 2) * 128);
        cp_commit();           // keep group count aligned (may be empty)

        const unsigned sOff = (unsigned)((it % 3) * STAGE);
        #pragma unroll
        for (int c = 0; c < 8; c++) {          // eight k16 chunks
            unsigned ah[4], al[4], bh[4], bl[4];
            ldsm4(ah, aBase + sOff + c * 32);
            ldsm4(al, aBase + sOff + A_PL + c * 32);
            ldsm4t(bh, bBase + sOff + c * (16 * BPITCH));
            ldsm4t(bl, bBase + sOff + B_PL + c * (16 * BPITCH));
            #pragma unroll
            for (int j = 0; j < 2; j++) {
                mma16816(accH[j], ah, bh + 2 * j);
                mma16816(accX[j], ah, bl + 2 * j);
                mma16816(accX[j], al, bh + 2 * j);
            }
        }
    }

    const int mBase = m0 + wm * 16 + (lane >> 2);
    #pragma unroll
    for (int j = 0; j < 2; j++) {
        const int nBase = n0 + wn * 16 + j * 8 + 2 * (lane & 3);
        #pragma unroll
        for (int h = 0; h < 2; h++) {
            const int m = mBase + h * 8;
            float d0 = accH[j][2 * h + 0] + accX[j][2 * h + 0];
            float d1 = accH[j][2 * h + 1] + accX[j][2 * h + 1];
            float* p = C + (size_t)m * ldc + nBase;
            float2 z = *(float2*)p;
            float o0 = tanhf(z.x + d0);
            float o1 = tanhf(z.y + d1);
            *(float2*)p = make_float2(o0, o1);
            unsigned hi, lo;
            split2(o0, o1, hi, lo);
            *(unsigned*)((char*)Hhi_o + ((size_t)m * N + nBase) * 2) = hi;
            *(unsigned*)((char*)Hlo_o + ((size_t)m * N + nBase) * 2) = lo;
        }
    }
}

// ---------------------------------------------------------------------------
// Launch.
// Inputs: 0 inputs [B,T,D]  1 h0 [B,U]  2 kernel [D,U]  3 rec_kernel [U,U]
//         4 bias [U]  5 mu_c [U]  6 sigma_c [U]  7 mu_p [U]  8 sigma_p [U]
// Output: [B,T,U] float32.
// ---------------------------------------------------------------------------
extern "C" void kernel_launch(void* const* d_in, const int* in_sizes, int n_in,
                              void* d_out, int out_size) {
    const float* X    = (const float*)d_in[0];
    const float* h0   = (const float*)d_in[1];
    const float* Wk   = (const float*)d_in[2];
    const float* Wr   = (const float*)d_in[3];
    const float* bias = (const float*)d_in[4];
    const float* muc  = (const float*)d_in[5];
    const float* sic  = (const float*)d_in[6];
    const float* mup  = (const float*)d_in[7];
    const float* sip  = (const float*)d_in[8];
    float* out = (float*)d_out;

    const int U = in_sizes[4];
    const int D = in_sizes[2] / U;
    const int B = in_sizes[1] / U;
    const int T = in_sizes[0] / (B * D);

    __nv_bfloat16 *Wc_hi, *Wc_lo, *Wp_hi, *Wp_lo, *Hhi, *Hlo;
    cudaGetSymbolAddress((void**)&Wc_hi, g_Wc_hi);
    cudaGetSymbolAddress((void**)&Wc_lo, g_Wc_lo);
    cudaGetSymbolAddress((void**)&Wp_hi, g_Wp_hi);
    cudaGetSymbolAddress((void**)&Wp_lo, g_Wp_lo);
    cudaGetSymbolAddress((void**)&Hhi, g_h_hi);
    cudaGetSymbolAddress((void**)&Hlo, g_h_lo);
    const size_t HPLANE = (size_t)256 * 1024;

    const int SMEM_BIG  = 2 * (2 * 64 * 112 + 2 * 32 * 144);      // 47104
    const int SMEM_STEP = 3 * (2 * 32 * 272 + 2 * 128 * 144);     // 162816
    static int s_init_done = 0;
    if (!s_init_done) {
        cudaFuncSetAttribute(mma_gemm_big,
                             cudaFuncAttributeMaxDynamicSharedMemorySize, SMEM_BIG);
        cudaFuncSetAttribute(mma_gemm_step,
                             cudaFuncAttributeMaxDynamicSharedMemorySize, SMEM_STEP);
        s_init_done = 1;
    }

    const float scale = sqrtf((float)D);  // reference uses sqrt(D) for BOTH masks

    // 1) Masked weights, split to bf16 hi/lo; h0 split into buffer 1.
    build_mask_kernel<<<U, 256>>>(Wk, muc, sic, Wc_hi, Wc_lo, D, U, scale);
    build_mask_kernel<<<U, 256>>>(Wr, mup, sip, Wp_hi, Wp_lo, U, U, scale);
    {
        int n = B * U;
        h0_split_kernel<<<(n / 2 + 255) / 256, 256>>>(
            h0, Hhi + HPLANE, Hlo + HPLANE, n);
    }

    // 2) Z = X @ Wc + bias -> straight into d_out.
    {
        dim3 grid(U / 64, (B * T) / 64);     // 16 x 2048
        mma_gemm_big<<<grid, 128, SMEM_BIG>>>(
            X, (size_t)D, Wc_hi, Wc_lo, bias, out, (size_t)U, U, D);
    }

    // 3) Recurrent scan. Step t reads h buffer (t+1)&1, writes t&1.
    {
        dim3 grid(U / 64, B / 32);           // 16 x 8 = 128 CTAs
        const size_t ldo = (size_t)T * U;
        for (int t = 0; t < T; t++) {
            const int rb = (t + 1) & 1;
            const int wb = t & 1;
            float* Ct = out + (size_t)t * U;
            mma_gemm_step<<<grid, 256, SMEM_STEP>>>(
                Hhi + rb * HPLANE, Hlo + rb * HPLANE,
                Wp_hi, Wp_lo,
                Ct, ldo,
                Hhi + wb * HPLANE, Hlo + wb * HPLANE,
                U, U);
        }
    }
}